// round 1
// baseline (speedup 1.0000x reference)
#include <cuda_runtime.h>

#define Bdim 8
#define Tdim 2048
#define Cdim 1024
#define Hdim 128
#define BT (Bdim*Tdim)

// Scratch for projected Q, K, V (8 MB each) — device globals, allocation-free.
__device__ float g_Q[BT * Hdim];
__device__ float g_K[BT * Hdim];
__device__ float g_V[BT * Hdim];

// ---------------------------------------------------------------------------
// Kernel 1: fused QKV projection.  grid = (BT/64, 3), block = 256.
// Each block computes a 64x128 output tile of one of Q/K/V.
// ---------------------------------------------------------------------------
__global__ __launch_bounds__(256) void qkv_kernel(
    const float* __restrict__ x, const float* __restrict__ Wq,
    const float* __restrict__ Wk, const float* __restrict__ Wv)
{
    __shared__ float As[32][64];    // [k][m] (transposed for broadcast reads)
    __shared__ float Bs[32][128];   // [k][n]

    const int m0 = blockIdx.x * 64;
    const float* W;
    float* out;
    if (blockIdx.y == 0)      { W = Wq; out = g_Q; }
    else if (blockIdx.y == 1) { W = Wk; out = g_K; }
    else                      { W = Wv; out = g_V; }

    const int tid  = threadIdx.x;
    const int wid  = tid >> 5;
    const int lane = tid & 31;

    float acc[8][4];
    #pragma unroll
    for (int i = 0; i < 8; i++)
        #pragma unroll
        for (int j = 0; j < 4; j++) acc[i][j] = 0.f;

    for (int k0 = 0; k0 < Cdim; k0 += 32) {
        // Load A tile (64 rows x 32 k): 512 float4, 2 per thread, coalesced.
        #pragma unroll
        for (int t = 0; t < 2; t++) {
            int idx = t * 256 + tid;
            int row = idx >> 3;
            int c4  = idx & 7;
            float4 a = *(const float4*)(x + (size_t)(m0 + row) * Cdim + k0 + c4 * 4);
            As[c4*4+0][row] = a.x;
            As[c4*4+1][row] = a.y;
            As[c4*4+2][row] = a.z;
            As[c4*4+3][row] = a.w;
        }
        // Load B tile (32 k x 128 n): 1024 float4, 4 per thread, coalesced.
        #pragma unroll
        for (int t = 0; t < 4; t++) {
            int idx = t * 256 + tid;
            int kr  = idx >> 5;
            int c4  = idx & 31;
            *(float4*)&Bs[kr][c4*4] =
                *(const float4*)(W + (size_t)(k0 + kr) * Hdim + c4 * 4);
        }
        __syncthreads();

        #pragma unroll
        for (int k = 0; k < 32; k++) {
            float4 a0 = *(const float4*)&As[k][wid*8];
            float4 a1 = *(const float4*)&As[k][wid*8+4];
            float4 b  = *(const float4*)&Bs[k][lane*4];
            float av[8] = {a0.x,a0.y,a0.z,a0.w,a1.x,a1.y,a1.z,a1.w};
            float bv[4] = {b.x,b.y,b.z,b.w};
            #pragma unroll
            for (int i = 0; i < 8; i++)
                #pragma unroll
                for (int j = 0; j < 4; j++)
                    acc[i][j] = fmaf(av[i], bv[j], acc[i][j]);
        }
        __syncthreads();
    }

    #pragma unroll
    for (int i = 0; i < 8; i++) {
        int row = m0 + wid*8 + i;
        float4 o = {acc[i][0], acc[i][1], acc[i][2], acc[i][3]};
        *(float4*)(out + (size_t)row * Hdim + lane * 4) = o;
    }
}

// ---------------------------------------------------------------------------
// Kernel 2: causal flash attention.  grid = (T/64, B), block = 256.
// Query tile of 64 rows; iterate key tiles 0..diag with online softmax.
// Warp w owns rows w*8..w*8+7 of the tile throughout.
// ---------------------------------------------------------------------------
__global__ __launch_bounds__(256) void attn_kernel(float* __restrict__ out)
{
    extern __shared__ float smem[];
    float (*Qs)[Hdim] = (float(*)[Hdim])smem;                          // 64x128
    float (*Kst)[64]  = (float(*)[64])(smem + 64*Hdim);                // 128x64 (h-major)
    float (*Vs)[Hdim] = (float(*)[Hdim])(smem + 64*Hdim + Hdim*64);    // 64x128
    float (*Ps)[64]   = (float(*)[64])(smem + 64*Hdim*2 + Hdim*64);    // 64x64

    const int b  = blockIdx.y;
    const int m0 = (gridDim.x - 1 - (int)blockIdx.x) * 64;  // heavy tiles first
    const float* Q = g_Q + (size_t)b * Tdim * Hdim;
    const float* K = g_K + (size_t)b * Tdim * Hdim;
    const float* V = g_V + (size_t)b * Tdim * Hdim;

    const int tid  = threadIdx.x;
    const int wid  = tid >> 5;
    const int lane = tid & 31;
    const float scale = 0.08838834764831845f;  // 1/sqrt(128)

    // Load Q tile, pre-scaled.
    #pragma unroll
    for (int t = 0; t < 8; t++) {
        int idx = t * 256 + tid;
        int row = idx >> 5;
        int c4  = idx & 31;
        float4 q = *(const float4*)(Q + (size_t)(m0 + row) * Hdim + c4 * 4);
        q.x *= scale; q.y *= scale; q.z *= scale; q.w *= scale;
        *(float4*)&Qs[row][c4*4] = q;
    }

    float accO[8][4];
    float mrow[8], lrow[8];
    #pragma unroll
    for (int i = 0; i < 8; i++) {
        mrow[i] = -1e30f; lrow[i] = 0.f;
        #pragma unroll
        for (int j = 0; j < 4; j++) accO[i][j] = 0.f;
    }

    const int ntiles = m0 / 64 + 1;
    for (int jt = 0; jt < ntiles; jt++) {
        const int n0 = jt * 64;
        __syncthreads();  // guards Qs (iter 0) and Kst/Vs reuse (iter > 0)

        // Load K (transposed -> Kst[h][n]) and V (row-major).
        #pragma unroll
        for (int t = 0; t < 8; t++) {
            int idx = t * 256 + tid;
            int n   = idx >> 5;
            int c4  = idx & 31;
            float4 kv = *(const float4*)(K + (size_t)(n0 + n) * Hdim + c4 * 4);
            Kst[c4*4+0][n] = kv.x;
            Kst[c4*4+1][n] = kv.y;
            Kst[c4*4+2][n] = kv.z;
            Kst[c4*4+3][n] = kv.w;
            *(float4*)&Vs[n][c4*4] =
                *(const float4*)(V + (size_t)(n0 + n) * Hdim + c4 * 4);
        }
        __syncthreads();

        // S = Qs . K^T ; lane covers cols (lane, lane+32).
        float s[8][2];
        #pragma unroll
        for (int i = 0; i < 8; i++) { s[i][0] = 0.f; s[i][1] = 0.f; }

        for (int h = 0; h < Hdim; h += 4) {
            float k0a = Kst[h+0][lane], k0b = Kst[h+0][lane+32];
            float k1a = Kst[h+1][lane], k1b = Kst[h+1][lane+32];
            float k2a = Kst[h+2][lane], k2b = Kst[h+2][lane+32];
            float k3a = Kst[h+3][lane], k3b = Kst[h+3][lane+32];
            #pragma unroll
            for (int i = 0; i < 8; i++) {
                float4 q = *(const float4*)&Qs[wid*8+i][h];
                s[i][0] = fmaf(q.x,k0a,fmaf(q.y,k1a,fmaf(q.z,k2a,fmaf(q.w,k3a,s[i][0]))));
                s[i][1] = fmaf(q.x,k0b,fmaf(q.y,k1b,fmaf(q.z,k2b,fmaf(q.w,k3b,s[i][1]))));
            }
        }

        // Causal mask (only the diagonal tile needs it).
        if (n0 == m0) {
            #pragma unroll
            for (int i = 0; i < 8; i++) {
                int row = m0 + wid*8 + i;
                if (n0 + lane      > row) s[i][0] = -1e30f;
                if (n0 + lane + 32 > row) s[i][1] = -1e30f;
            }
        }

        // Online softmax per row; store P to warp-local smem.
        #pragma unroll
        for (int i = 0; i < 8; i++) {
            float mx = fmaxf(s[i][0], s[i][1]);
            #pragma unroll
            for (int off = 16; off > 0; off >>= 1)
                mx = fmaxf(mx, __shfl_xor_sync(0xffffffffu, mx, off));
            float mnew = fmaxf(mrow[i], mx);
            float corr = __expf(mrow[i] - mnew);
            float p0 = __expf(s[i][0] - mnew);
            float p1 = __expf(s[i][1] - mnew);
            float rs = p0 + p1;
            #pragma unroll
            for (int off = 16; off > 0; off >>= 1)
                rs += __shfl_xor_sync(0xffffffffu, rs, off);
            lrow[i] = lrow[i] * corr + rs;
            mrow[i] = mnew;
            #pragma unroll
            for (int j = 0; j < 4; j++) accO[i][j] *= corr;
            Ps[wid*8+i][lane]      = p0;
            Ps[wid*8+i][lane + 32] = p1;
        }
        __syncwarp();  // Ps is warp-local (rows owned by this warp)

        // O += P . V ; lane covers output cols lane*4..lane*4+3.
        #pragma unroll 4
        for (int n = 0; n < 64; n++) {
            float4 v = *(const float4*)&Vs[n][lane*4];
            #pragma unroll
            for (int i = 0; i < 8; i++) {
                float p = Ps[wid*8+i][n];
                accO[i][0] = fmaf(p, v.x, accO[i][0]);
                accO[i][1] = fmaf(p, v.y, accO[i][1]);
                accO[i][2] = fmaf(p, v.z, accO[i][2]);
                accO[i][3] = fmaf(p, v.w, accO[i][3]);
            }
        }
    }

    // Final normalize + store.
    #pragma unroll
    for (int i = 0; i < 8; i++) {
        float inv = 1.f / lrow[i];
        int row = m0 + wid*8 + i;
        float4 o = {accO[i][0]*inv, accO[i][1]*inv, accO[i][2]*inv, accO[i][3]*inv};
        *(float4*)(out + ((size_t)b * Tdim + row) * Hdim + lane * 4) = o;
    }
}

// ---------------------------------------------------------------------------
extern "C" void kernel_launch(void* const* d_in, const int* in_sizes, int n_in,
                              void* d_out, int out_size)
{
    const float* x  = (const float*)d_in[0];
    const float* Wq = (const float*)d_in[1];
    const float* Wk = (const float*)d_in[2];
    const float* Wv = (const float*)d_in[3];
    float* out = (float*)d_out;

    dim3 g1(BT / 64, 3);
    qkv_kernel<<<g1, 256>>>(x, Wq, Wk, Wv);

    const int smem_bytes = (64*Hdim*2 + Hdim*64 + 64*64) * (int)sizeof(float); // 114688
    cudaFuncSetAttribute(attn_kernel,
                         cudaFuncAttributeMaxDynamicSharedMemorySize, smem_bytes);
    dim3 g2(Tdim / 64, Bdim);
    attn_kernel<<<g2, 256, smem_bytes>>>(out);
}

// round 2
// speedup vs baseline: 3.8165x; 3.8165x over previous
#include <cuda_runtime.h>
#include <cstdint>

#define Bdim 8
#define Tdim 2048
#define Cdim 1024
#define Hdim 128
#define BT (Bdim*Tdim)

// Scratch for projected Q, K, V (8 MB each) — device globals, allocation-free.
__device__ float g_Q[BT * Hdim];
__device__ float g_K[BT * Hdim];
__device__ float g_V[BT * Hdim];

// ---------------------------------------------------------------------------
// TF32 helpers
// ---------------------------------------------------------------------------
__device__ __forceinline__ uint32_t cvt_tf32(float x) {
    uint32_t u;
    asm("cvt.rna.tf32.f32 %0, %1;" : "=r"(u) : "f"(x));
    return u;
}
__device__ __forceinline__ float cvt_tf32f(float x) {
    return __uint_as_float(cvt_tf32(x));
}
// D += A(16x8) * B(8x8), tf32, fp32 accum.
__device__ __forceinline__ void mma_tf32(float* d, const uint32_t* a,
                                         uint32_t b0, uint32_t b1) {
    asm volatile(
        "mma.sync.aligned.m16n8k8.row.col.f32.tf32.tf32.f32 "
        "{%0,%1,%2,%3}, {%4,%5,%6,%7}, {%8,%9}, {%0,%1,%2,%3};"
        : "+f"(d[0]), "+f"(d[1]), "+f"(d[2]), "+f"(d[3])
        : "r"(a[0]), "r"(a[1]), "r"(a[2]), "r"(a[3]), "r"(b0), "r"(b1));
}

// ---------------------------------------------------------------------------
// Kernel 1: fused QKV projection, TF32 MMA.
// grid = (BT/128, 3), block = 128 (4 warps). CTA tile 128x128, warp 32x128.
// ---------------------------------------------------------------------------
__global__ __launch_bounds__(128) void qkv_kernel(
    const float* __restrict__ x, const float* __restrict__ Wq,
    const float* __restrict__ Wk, const float* __restrict__ Wv)
{
    __shared__ float As[128 * 36];   // x tile [128 rows][32 k], pad 36
    __shared__ float Bs[32 * 136];   // W tile [32 k][128 n],   pad 136

    const int m0 = blockIdx.x * 128;
    const float* W;
    float* outp;
    if (blockIdx.y == 0)      { W = Wq; outp = g_Q; }
    else if (blockIdx.y == 1) { W = Wk; outp = g_K; }
    else                      { W = Wv; outp = g_V; }

    const int tid  = threadIdx.x;
    const int wid  = tid >> 5;
    const int lane = tid & 31;
    const int g    = lane >> 2;   // groupID
    const int tg   = lane & 3;    // threadID in group

    float oc[2][16][4];
    #pragma unroll
    for (int mb = 0; mb < 2; mb++)
        #pragma unroll
        for (int nb = 0; nb < 16; nb++)
            #pragma unroll
            for (int c = 0; c < 4; c++) oc[mb][nb][c] = 0.f;

    for (int kc = 0; kc < 32; kc++) {
        __syncthreads();
        // Stage x tile (128x32) -> As (tf32), coalesced float4.
        #pragma unroll
        for (int tt = 0; tt < 8; tt++) {
            int idx = tt * 128 + tid;
            int row = idx >> 3, c4 = idx & 7;
            float4 a = *(const float4*)(x + (size_t)(m0 + row) * Cdim + kc * 32 + c4 * 4);
            float4 t = {cvt_tf32f(a.x), cvt_tf32f(a.y), cvt_tf32f(a.z), cvt_tf32f(a.w)};
            *(float4*)&As[row * 36 + c4 * 4] = t;
        }
        // Stage W tile (32x128) -> Bs (tf32).
        #pragma unroll
        for (int tt = 0; tt < 8; tt++) {
            int idx = tt * 128 + tid;
            int row = idx >> 5, c4 = idx & 31;
            float4 b = *(const float4*)(W + (size_t)(kc * 32 + row) * Hdim + c4 * 4);
            float4 t = {cvt_tf32f(b.x), cvt_tf32f(b.y), cvt_tf32f(b.z), cvt_tf32f(b.w)};
            *(float4*)&Bs[row * 136 + c4 * 4] = t;
        }
        __syncthreads();

        #pragma unroll
        for (int ks = 0; ks < 4; ks++) {
            const int k = ks * 8;
            uint32_t a0[4], a1[4];
            int r0 = wid * 32 + g;
            a0[0] = __float_as_uint(As[(r0     ) * 36 + k + tg    ]);
            a0[1] = __float_as_uint(As[(r0 +  8) * 36 + k + tg    ]);
            a0[2] = __float_as_uint(As[(r0     ) * 36 + k + tg + 4]);
            a0[3] = __float_as_uint(As[(r0 +  8) * 36 + k + tg + 4]);
            a1[0] = __float_as_uint(As[(r0 + 16) * 36 + k + tg    ]);
            a1[1] = __float_as_uint(As[(r0 + 24) * 36 + k + tg    ]);
            a1[2] = __float_as_uint(As[(r0 + 16) * 36 + k + tg + 4]);
            a1[3] = __float_as_uint(As[(r0 + 24) * 36 + k + tg + 4]);
            #pragma unroll
            for (int nb = 0; nb < 16; nb++) {
                uint32_t b0 = __float_as_uint(Bs[(k + tg    ) * 136 + nb * 8 + g]);
                uint32_t b1 = __float_as_uint(Bs[(k + tg + 4) * 136 + nb * 8 + g]);
                mma_tf32(oc[0][nb], a0, b0, b1);
                mma_tf32(oc[1][nb], a1, b0, b1);
            }
        }
    }

    // Store: rows w*32 + mb*16 + g (+8), cols nb*8 + 2tg (+1).
    #pragma unroll
    for (int mb = 0; mb < 2; mb++) {
        int r0 = m0 + wid * 32 + mb * 16 + g;
        #pragma unroll
        for (int nb = 0; nb < 16; nb++) {
            float2 lo = {oc[mb][nb][0], oc[mb][nb][1]};
            float2 hi = {oc[mb][nb][2], oc[mb][nb][3]};
            *(float2*)(outp + (size_t)(r0    ) * Hdim + nb * 8 + 2 * tg) = lo;
            *(float2*)(outp + (size_t)(r0 + 8) * Hdim + nb * 8 + 2 * tg) = hi;
        }
    }
}

// ---------------------------------------------------------------------------
// Kernel 2: causal flash attention, TF32 MMA.
// grid = (16, B), block = 128 (4 warps). Each CTA does q-tiles (j, 31-j)
// sequentially -> uniform 33 kv-tiles per CTA. Q tile 64 rows, kv tile 64.
// Warp w owns rows w*16..w*16+15.
// ---------------------------------------------------------------------------
#define KS_PAD 132
#define VS_PAD 136
#define PS_PAD 68

__global__ __launch_bounds__(128) void attn_kernel(float* __restrict__ out)
{
    extern __shared__ float smem[];
    float* Ks = smem;                                // [64][132]
    float* Vs = smem + 64 * KS_PAD;                  // [64][136]
    float* Ps = smem + 64 * KS_PAD + 64 * VS_PAD;    // [64][68]

    const int b    = blockIdx.y;
    const int tid  = threadIdx.x;
    const int wid  = tid >> 5;
    const int lane = tid & 31;
    const int g    = lane >> 2;
    const int tg   = lane & 3;
    const float scale = 0.08838834764831845f;  // 1/sqrt(128)

    const float* Q = g_Q + (size_t)b * Tdim * Hdim;
    const float* K = g_K + (size_t)b * Tdim * Hdim;
    const float* V = g_V + (size_t)b * Tdim * Hdim;

    #pragma unroll 1
    for (int phase = 0; phase < 2; phase++) {
        const int qt = phase == 0 ? (int)blockIdx.x : 31 - (int)blockIdx.x;
        const int m0 = qt * 64;

        __syncthreads();  // all warps done with previous phase's smem
        // Stage Q tile (64x128, pre-scaled, tf32) into Ks.
        #pragma unroll
        for (int tt = 0; tt < 16; tt++) {
            int idx = tt * 128 + tid;
            int row = idx >> 5, c4 = idx & 31;
            float4 q = *(const float4*)(Q + (size_t)(m0 + row) * Hdim + c4 * 4);
            float4 t = {cvt_tf32f(q.x * scale), cvt_tf32f(q.y * scale),
                        cvt_tf32f(q.z * scale), cvt_tf32f(q.w * scale)};
            *(float4*)&Ks[row * KS_PAD + c4 * 4] = t;
        }
        __syncthreads();

        // Q A-fragments: 16 k-steps x 4 regs.
        uint32_t qf[16][4];
        {
            int r0 = wid * 16 + g;
            #pragma unroll
            for (int ks = 0; ks < 16; ks++) {
                int k = ks * 8;
                qf[ks][0] = __float_as_uint(Ks[(r0    ) * KS_PAD + k + tg    ]);
                qf[ks][1] = __float_as_uint(Ks[(r0 + 8) * KS_PAD + k + tg    ]);
                qf[ks][2] = __float_as_uint(Ks[(r0    ) * KS_PAD + k + tg + 4]);
                qf[ks][3] = __float_as_uint(Ks[(r0 + 8) * KS_PAD + k + tg + 4]);
            }
        }

        float of[16][4];
        #pragma unroll
        for (int nb = 0; nb < 16; nb++)
            #pragma unroll
            for (int c = 0; c < 4; c++) of[nb][c] = 0.f;
        float mrow0 = -1e30f, mrow1 = -1e30f, lrow0 = 0.f, lrow1 = 0.f;

        #pragma unroll 1
        for (int jt = 0; jt <= qt; jt++) {
            const int n0 = jt * 64;
            __syncthreads();  // previous iter's Ks/Vs reads done (and qf loads)
            // Stage K, V tiles (64x128 each, tf32).
            #pragma unroll
            for (int tt = 0; tt < 16; tt++) {
                int idx = tt * 128 + tid;
                int row = idx >> 5, c4 = idx & 31;
                float4 kk = *(const float4*)(K + (size_t)(n0 + row) * Hdim + c4 * 4);
                float4 tk = {cvt_tf32f(kk.x), cvt_tf32f(kk.y), cvt_tf32f(kk.z), cvt_tf32f(kk.w)};
                *(float4*)&Ks[row * KS_PAD + c4 * 4] = tk;
                float4 vv = *(const float4*)(V + (size_t)(n0 + row) * Hdim + c4 * 4);
                float4 tv = {cvt_tf32f(vv.x), cvt_tf32f(vv.y), cvt_tf32f(vv.z), cvt_tf32f(vv.w)};
                *(float4*)&Vs[row * VS_PAD + c4 * 4] = tv;
            }
            __syncthreads();

            // S = Q . K^T  (16x64 per warp)
            float sacc[8][4];
            #pragma unroll
            for (int nb = 0; nb < 8; nb++)
                #pragma unroll
                for (int c = 0; c < 4; c++) sacc[nb][c] = 0.f;

            #pragma unroll
            for (int ks = 0; ks < 16; ks++) {
                const int k = ks * 8;
                #pragma unroll
                for (int nb = 0; nb < 8; nb++) {
                    uint32_t b0 = __float_as_uint(Ks[(nb * 8 + g) * KS_PAD + k + tg    ]);
                    uint32_t b1 = __float_as_uint(Ks[(nb * 8 + g) * KS_PAD + k + tg + 4]);
                    mma_tf32(sacc[nb], qf[ks], b0, b1);
                }
            }

            // Causal mask (diagonal tile only).
            if (jt == qt) {
                const int row0 = m0 + wid * 16 + g;
                const int row1 = row0 + 8;
                #pragma unroll
                for (int nb = 0; nb < 8; nb++) {
                    int c0 = n0 + nb * 8 + 2 * tg;
                    if (c0     > row0) sacc[nb][0] = -1e30f;
                    if (c0 + 1 > row0) sacc[nb][1] = -1e30f;
                    if (c0     > row1) sacc[nb][2] = -1e30f;
                    if (c0 + 1 > row1) sacc[nb][3] = -1e30f;
                }
            }

            // Online softmax. Row r0=g handled by quad lanes (shuffle xor 1,2).
            float mx0 = -1e30f, mx1 = -1e30f;
            #pragma unroll
            for (int nb = 0; nb < 8; nb++) {
                mx0 = fmaxf(mx0, fmaxf(sacc[nb][0], sacc[nb][1]));
                mx1 = fmaxf(mx1, fmaxf(sacc[nb][2], sacc[nb][3]));
            }
            mx0 = fmaxf(mx0, __shfl_xor_sync(0xffffffffu, mx0, 1));
            mx0 = fmaxf(mx0, __shfl_xor_sync(0xffffffffu, mx0, 2));
            mx1 = fmaxf(mx1, __shfl_xor_sync(0xffffffffu, mx1, 1));
            mx1 = fmaxf(mx1, __shfl_xor_sync(0xffffffffu, mx1, 2));

            float mn0 = fmaxf(mrow0, mx0), mn1 = fmaxf(mrow1, mx1);
            float corr0 = __expf(mrow0 - mn0), corr1 = __expf(mrow1 - mn1);
            float rs0 = 0.f, rs1 = 0.f;
            const int pr0 = wid * 16 + g;
            #pragma unroll
            for (int nb = 0; nb < 8; nb++) {
                float p00 = cvt_tf32f(__expf(sacc[nb][0] - mn0));
                float p01 = cvt_tf32f(__expf(sacc[nb][1] - mn0));
                float p10 = cvt_tf32f(__expf(sacc[nb][2] - mn1));
                float p11 = cvt_tf32f(__expf(sacc[nb][3] - mn1));
                rs0 += p00 + p01;
                rs1 += p10 + p11;
                float2 lo = {p00, p01}, hi = {p10, p11};
                *(float2*)&Ps[(pr0    ) * PS_PAD + nb * 8 + 2 * tg] = lo;
                *(float2*)&Ps[(pr0 + 8) * PS_PAD + nb * 8 + 2 * tg] = hi;
            }
            rs0 += __shfl_xor_sync(0xffffffffu, rs0, 1);
            rs0 += __shfl_xor_sync(0xffffffffu, rs0, 2);
            rs1 += __shfl_xor_sync(0xffffffffu, rs1, 1);
            rs1 += __shfl_xor_sync(0xffffffffu, rs1, 2);
            lrow0 = lrow0 * corr0 + rs0;
            lrow1 = lrow1 * corr1 + rs1;
            mrow0 = mn0; mrow1 = mn1;
            #pragma unroll
            for (int nb = 0; nb < 16; nb++) {
                of[nb][0] *= corr0; of[nb][1] *= corr0;
                of[nb][2] *= corr1; of[nb][3] *= corr1;
            }
            __syncwarp();  // Ps rows are warp-local

            // O += P . V  (16x128 per warp)
            #pragma unroll
            for (int ks = 0; ks < 8; ks++) {
                const int k = ks * 8;
                uint32_t pa[4];
                pa[0] = __float_as_uint(Ps[(pr0    ) * PS_PAD + k + tg    ]);
                pa[1] = __float_as_uint(Ps[(pr0 + 8) * PS_PAD + k + tg    ]);
                pa[2] = __float_as_uint(Ps[(pr0    ) * PS_PAD + k + tg + 4]);
                pa[3] = __float_as_uint(Ps[(pr0 + 8) * PS_PAD + k + tg + 4]);
                #pragma unroll
                for (int nb = 0; nb < 16; nb++) {
                    uint32_t b0 = __float_as_uint(Vs[(k + tg    ) * VS_PAD + nb * 8 + g]);
                    uint32_t b1 = __float_as_uint(Vs[(k + tg + 4) * VS_PAD + nb * 8 + g]);
                    mma_tf32(of[nb], pa, b0, b1);
                }
            }
        }

        // Normalize + store.
        float inv0 = 1.f / lrow0, inv1 = 1.f / lrow1;
        int r0 = m0 + wid * 16 + g;
        #pragma unroll
        for (int nb = 0; nb < 16; nb++) {
            float2 lo = {of[nb][0] * inv0, of[nb][1] * inv0};
            float2 hi = {of[nb][2] * inv1, of[nb][3] * inv1};
            *(float2*)(out + ((size_t)b * Tdim + r0    ) * Hdim + nb * 8 + 2 * tg) = lo;
            *(float2*)(out + ((size_t)b * Tdim + r0 + 8) * Hdim + nb * 8 + 2 * tg) = hi;
        }
    }
}

// ---------------------------------------------------------------------------
extern "C" void kernel_launch(void* const* d_in, const int* in_sizes, int n_in,
                              void* d_out, int out_size)
{
    const float* x  = (const float*)d_in[0];
    const float* Wq = (const float*)d_in[1];
    const float* Wk = (const float*)d_in[2];
    const float* Wv = (const float*)d_in[3];
    float* out = (float*)d_out;

    dim3 g1(BT / 128, 3);
    qkv_kernel<<<g1, 128>>>(x, Wq, Wk, Wv);

    const int smem_bytes = (64 * KS_PAD + 64 * VS_PAD + 64 * PS_PAD) * (int)sizeof(float);
    cudaFuncSetAttribute(attn_kernel,
                         cudaFuncAttributeMaxDynamicSharedMemorySize, smem_bytes);
    dim3 g2(16, Bdim);
    attn_kernel<<<g2, 128, smem_bytes>>>(out);
}

// round 3
// speedup vs baseline: 5.1072x; 1.3382x over previous
#include <cuda_runtime.h>
#include <cstdint>

#define Bdim 8
#define Tdim 2048
#define Cdim 1024
#define Hdim 128
#define BT (Bdim*Tdim)

// Scratch for projected Q (pre-scaled), K, V — stored as tf32-rounded fp32.
__device__ float g_Q[BT * Hdim];
__device__ float g_K[BT * Hdim];
__device__ float g_V[BT * Hdim];

// ---------------------------------------------------------------------------
// Helpers
// ---------------------------------------------------------------------------
__device__ __forceinline__ uint32_t cvt_tf32(float x) {
    uint32_t u;
    asm("cvt.rna.tf32.f32 %0, %1;" : "=r"(u) : "f"(x));
    return u;
}
__device__ __forceinline__ float cvt_tf32f(float x) {
    return __uint_as_float(cvt_tf32(x));
}
// D += A(16x8) * B(8x8), tf32, fp32 accum.
__device__ __forceinline__ void mma_tf32(float* d, const uint32_t* a,
                                         uint32_t b0, uint32_t b1) {
    asm volatile(
        "mma.sync.aligned.m16n8k8.row.col.f32.tf32.tf32.f32 "
        "{%0,%1,%2,%3}, {%4,%5,%6,%7}, {%8,%9}, {%0,%1,%2,%3};"
        : "+f"(d[0]), "+f"(d[1]), "+f"(d[2]), "+f"(d[3])
        : "r"(a[0]), "r"(a[1]), "r"(a[2]), "r"(a[3]), "r"(b0), "r"(b1));
}
__device__ __forceinline__ uint32_t s2u(const void* p) {
    return (uint32_t)__cvta_generic_to_shared(p);
}
__device__ __forceinline__ void cpa16(uint32_t dst, const void* src) {
    asm volatile("cp.async.cg.shared.global [%0], [%1], 16;" :: "r"(dst), "l"(src));
}
__device__ __forceinline__ void cpa_commit() {
    asm volatile("cp.async.commit_group;");
}
__device__ __forceinline__ void cpa_wait0() {
    asm volatile("cp.async.wait_group 0;");
}

// ---------------------------------------------------------------------------
// Kernel 1: fused QKV projection, TF32 MMA, cp.async double-buffered.
// grid = (BT/128, 3), block = 128 (4 warps). CTA tile 128x128, warp 32x128.
// Epilogue stores tf32-rounded values (Q additionally pre-scaled).
// ---------------------------------------------------------------------------
#define AS_PAD 36
#define BS_PAD 136

__global__ __launch_bounds__(128) void qkv_kernel(
    const float* __restrict__ x, const float* __restrict__ Wq,
    const float* __restrict__ Wk, const float* __restrict__ Wv)
{
    extern __shared__ float sm[];
    float* As[2] = { sm,                sm + 128 * AS_PAD };
    float* Bs[2] = { sm + 2*128*AS_PAD, sm + 2*128*AS_PAD + 32 * BS_PAD };

    const int m0 = blockIdx.x * 128;
    const float* W;
    float* outp;
    float osc;
    if (blockIdx.y == 0)      { W = Wq; outp = g_Q; osc = 0.08838834764831845f; }
    else if (blockIdx.y == 1) { W = Wk; outp = g_K; osc = 1.f; }
    else                      { W = Wv; outp = g_V; osc = 1.f; }

    const int tid  = threadIdx.x;
    const int wid  = tid >> 5;
    const int lane = tid & 31;
    const int g    = lane >> 2;
    const int tg   = lane & 3;

    // Per-thread staging coords.
    const int arow = tid >> 3, ac4 = tid & 7;    // A: 128 threads cover 128 f4; x8
    const int brow = tid >> 5, bc4 = tid & 31;   // B: 128 threads cover 128 f4; x8

    // Issue chunk 0.
    {
        uint32_t au = s2u(As[0]), bu = s2u(Bs[0]);
        #pragma unroll
        for (int tt = 0; tt < 8; tt++) {
            int row = arow + tt * 16;
            cpa16(au + (row * AS_PAD + ac4 * 4) * 4,
                  x + (size_t)(m0 + row) * Cdim + ac4 * 4);
        }
        #pragma unroll
        for (int tt = 0; tt < 8; tt++) {
            int row = brow + tt * 4;
            cpa16(bu + (row * BS_PAD + bc4 * 4) * 4,
                  W + (size_t)row * Hdim + bc4 * 4);
        }
        cpa_commit();
    }

    float oc[2][16][4];
    #pragma unroll
    for (int mb = 0; mb < 2; mb++)
        #pragma unroll
        for (int nb = 0; nb < 16; nb++)
            #pragma unroll
            for (int c = 0; c < 4; c++) oc[mb][nb][c] = 0.f;

    #pragma unroll 1
    for (int kc = 0; kc < 32; kc++) {
        cpa_wait0();
        __syncthreads();
        const int cur = kc & 1;
        if (kc + 1 < 32) {
            const int nxt = cur ^ 1;
            uint32_t au = s2u(As[nxt]), bu = s2u(Bs[nxt]);
            const int k0 = (kc + 1) * 32;
            #pragma unroll
            for (int tt = 0; tt < 8; tt++) {
                int row = arow + tt * 16;
                cpa16(au + (row * AS_PAD + ac4 * 4) * 4,
                      x + (size_t)(m0 + row) * Cdim + k0 + ac4 * 4);
            }
            #pragma unroll
            for (int tt = 0; tt < 8; tt++) {
                int row = brow + tt * 4;
                cpa16(bu + (row * BS_PAD + bc4 * 4) * 4,
                      W + (size_t)(k0 + row) * Hdim + bc4 * 4);
            }
            cpa_commit();
        }

        const float* A = As[cur];
        const float* B = Bs[cur];
        #pragma unroll
        for (int ks = 0; ks < 4; ks++) {
            const int k = ks * 8;
            const int r0 = wid * 32 + g;
            uint32_t a0[4], a1[4];
            a0[0] = cvt_tf32(A[(r0     ) * AS_PAD + k + tg    ]);
            a0[1] = cvt_tf32(A[(r0 +  8) * AS_PAD + k + tg    ]);
            a0[2] = cvt_tf32(A[(r0     ) * AS_PAD + k + tg + 4]);
            a0[3] = cvt_tf32(A[(r0 +  8) * AS_PAD + k + tg + 4]);
            a1[0] = cvt_tf32(A[(r0 + 16) * AS_PAD + k + tg    ]);
            a1[1] = cvt_tf32(A[(r0 + 24) * AS_PAD + k + tg    ]);
            a1[2] = cvt_tf32(A[(r0 + 16) * AS_PAD + k + tg + 4]);
            a1[3] = cvt_tf32(A[(r0 + 24) * AS_PAD + k + tg + 4]);
            #pragma unroll
            for (int nb = 0; nb < 16; nb++) {
                uint32_t b0 = cvt_tf32(B[(k + tg    ) * BS_PAD + nb * 8 + g]);
                uint32_t b1 = cvt_tf32(B[(k + tg + 4) * BS_PAD + nb * 8 + g]);
                mma_tf32(oc[0][nb], a0, b0, b1);
                mma_tf32(oc[1][nb], a1, b0, b1);
            }
        }
    }

    // Store tf32-rounded (Q pre-scaled).
    #pragma unroll
    for (int mb = 0; mb < 2; mb++) {
        int r0 = m0 + wid * 32 + mb * 16 + g;
        #pragma unroll
        for (int nb = 0; nb < 16; nb++) {
            float2 lo = {cvt_tf32f(oc[mb][nb][0] * osc), cvt_tf32f(oc[mb][nb][1] * osc)};
            float2 hi = {cvt_tf32f(oc[mb][nb][2] * osc), cvt_tf32f(oc[mb][nb][3] * osc)};
            *(float2*)(outp + (size_t)(r0    ) * Hdim + nb * 8 + 2 * tg) = lo;
            *(float2*)(outp + (size_t)(r0 + 8) * Hdim + nb * 8 + 2 * tg) = hi;
        }
    }
}

// ---------------------------------------------------------------------------
// Kernel 2: causal flash attention, TF32 MMA, cp.async double-buffered K/V.
// grid = (16, B), block = 128 (4 warps). CTA does q-tiles (j, 31-j) -> 33
// uniform kv-steps. Warp w owns rows w*16..w*16+15.
// ---------------------------------------------------------------------------
#define QS_PAD 132
#define KS_PAD 132
#define VS_PAD 136
#define PS_PAD 68

__global__ __launch_bounds__(128) void attn_kernel(float* __restrict__ out)
{
    extern __shared__ float smem[];
    float* Qs      = smem;                                   // [64][132]
    float* Kb[2]   = { smem + 64*QS_PAD,
                       smem + 64*QS_PAD + 64*KS_PAD };       // 2x [64][132]
    float* Vb[2]   = { smem + 64*QS_PAD + 2*64*KS_PAD,
                       smem + 64*QS_PAD + 2*64*KS_PAD + 64*VS_PAD }; // 2x [64][136]
    float* Ps      = smem + 64*QS_PAD + 2*64*KS_PAD + 2*64*VS_PAD;   // [64][68]

    const int b    = blockIdx.y;
    const int tid  = threadIdx.x;
    const int wid  = tid >> 5;
    const int lane = tid & 31;
    const int g    = lane >> 2;
    const int tg   = lane & 3;

    const float* Q = g_Q + (size_t)b * Tdim * Hdim;
    const float* K = g_K + (size_t)b * Tdim * Hdim;
    const float* V = g_V + (size_t)b * Tdim * Hdim;

    const int srow = tid >> 2, sc4g = (tid & 3) * 8;  // staging: 128 thr = 2048 f4 / 16

    #pragma unroll 1
    for (int phase = 0; phase < 2; phase++) {
        const int qt = phase == 0 ? (int)blockIdx.x : 31 - (int)blockIdx.x;
        const int m0 = qt * 64;

        __syncthreads();  // all warps done with previous phase's smem

        // Stage Q tile (already tf32 + pre-scaled) via cp.async.
        {
            uint32_t qu = s2u(Qs);
            #pragma unroll
            for (int tt = 0; tt < 16; tt++) {
                int idx = tt * 128 + tid;
                int row = idx >> 5, c4 = idx & 31;
                cpa16(qu + (row * QS_PAD + c4 * 4) * 4,
                      Q + (size_t)(m0 + row) * Hdim + c4 * 4);
            }
            cpa_commit();
        }
        // Stage K/V tile 0.
        {
            uint32_t ku = s2u(Kb[0]), vu = s2u(Vb[0]);
            #pragma unroll
            for (int tt = 0; tt < 16; tt++) {
                int idx = tt * 128 + tid;
                int row = idx >> 5, c4 = idx & 31;
                cpa16(ku + (row * KS_PAD + c4 * 4) * 4,
                      K + (size_t)row * Hdim + c4 * 4);
                cpa16(vu + (row * VS_PAD + c4 * 4) * 4,
                      V + (size_t)row * Hdim + c4 * 4);
            }
            cpa_commit();
        }

        float of[16][4];
        #pragma unroll
        for (int nb = 0; nb < 16; nb++)
            #pragma unroll
            for (int c = 0; c < 4; c++) of[nb][c] = 0.f;
        float mrow0 = -1e30f, mrow1 = -1e30f, lrow0 = 0.f, lrow1 = 0.f;

        const int r0q = wid * 16 + g;

        #pragma unroll 1
        for (int jt = 0; jt <= qt; jt++) {
            const int cur = jt & 1;
            cpa_wait0();       // current tile (and Q on jt==0) arrived
            __syncthreads();   // all warps done with buffer we're about to refill

            if (jt < qt) {
                const int n0n = (jt + 1) * 64;
                uint32_t ku = s2u(Kb[cur ^ 1]), vu = s2u(Vb[cur ^ 1]);
                #pragma unroll
                for (int tt = 0; tt < 16; tt++) {
                    int idx = tt * 128 + tid;
                    int row = idx >> 5, c4 = idx & 31;
                    cpa16(ku + (row * KS_PAD + c4 * 4) * 4,
                          K + (size_t)(n0n + row) * Hdim + c4 * 4);
                    cpa16(vu + (row * VS_PAD + c4 * 4) * 4,
                          V + (size_t)(n0n + row) * Hdim + c4 * 4);
                }
                cpa_commit();
            }

            const float* Kc = Kb[cur];
            const float* Vc = Vb[cur];

            // S = Q . K^T  (16x64 per warp)
            float sacc[8][4];
            #pragma unroll
            for (int nb = 0; nb < 8; nb++)
                #pragma unroll
                for (int c = 0; c < 4; c++) sacc[nb][c] = 0.f;

            #pragma unroll
            for (int ks = 0; ks < 16; ks++) {
                const int k = ks * 8;
                uint32_t qa[4];
                qa[0] = __float_as_uint(Qs[(r0q    ) * QS_PAD + k + tg    ]);
                qa[1] = __float_as_uint(Qs[(r0q + 8) * QS_PAD + k + tg    ]);
                qa[2] = __float_as_uint(Qs[(r0q    ) * QS_PAD + k + tg + 4]);
                qa[3] = __float_as_uint(Qs[(r0q + 8) * QS_PAD + k + tg + 4]);
                #pragma unroll
                for (int nb = 0; nb < 8; nb++) {
                    uint32_t b0 = __float_as_uint(Kc[(nb * 8 + g) * KS_PAD + k + tg    ]);
                    uint32_t b1 = __float_as_uint(Kc[(nb * 8 + g) * KS_PAD + k + tg + 4]);
                    mma_tf32(sacc[nb], qa, b0, b1);
                }
            }

            // Causal mask (diagonal tile only).
            if (jt == qt) {
                const int row0 = m0 + r0q;
                const int row1 = row0 + 8;
                const int n0 = jt * 64;
                #pragma unroll
                for (int nb = 0; nb < 8; nb++) {
                    int c0 = n0 + nb * 8 + 2 * tg;
                    if (c0     > row0) sacc[nb][0] = -1e30f;
                    if (c0 + 1 > row0) sacc[nb][1] = -1e30f;
                    if (c0     > row1) sacc[nb][2] = -1e30f;
                    if (c0 + 1 > row1) sacc[nb][3] = -1e30f;
                }
            }

            // Online softmax (rows r0q, r0q+8), quad reduction.
            float mx0 = -1e30f, mx1 = -1e30f;
            #pragma unroll
            for (int nb = 0; nb < 8; nb++) {
                mx0 = fmaxf(mx0, fmaxf(sacc[nb][0], sacc[nb][1]));
                mx1 = fmaxf(mx1, fmaxf(sacc[nb][2], sacc[nb][3]));
            }
            mx0 = fmaxf(mx0, __shfl_xor_sync(0xffffffffu, mx0, 1));
            mx0 = fmaxf(mx0, __shfl_xor_sync(0xffffffffu, mx0, 2));
            mx1 = fmaxf(mx1, __shfl_xor_sync(0xffffffffu, mx1, 1));
            mx1 = fmaxf(mx1, __shfl_xor_sync(0xffffffffu, mx1, 2));

            float mn0 = fmaxf(mrow0, mx0), mn1 = fmaxf(mrow1, mx1);
            float corr0 = __expf(mrow0 - mn0), corr1 = __expf(mrow1 - mn1);
            float rs0 = 0.f, rs1 = 0.f;
            #pragma unroll
            for (int nb = 0; nb < 8; nb++) {
                float p00 = cvt_tf32f(__expf(sacc[nb][0] - mn0));
                float p01 = cvt_tf32f(__expf(sacc[nb][1] - mn0));
                float p10 = cvt_tf32f(__expf(sacc[nb][2] - mn1));
                float p11 = cvt_tf32f(__expf(sacc[nb][3] - mn1));
                rs0 += p00 + p01;
                rs1 += p10 + p11;
                float2 lo = {p00, p01}, hi = {p10, p11};
                *(float2*)&Ps[(r0q    ) * PS_PAD + nb * 8 + 2 * tg] = lo;
                *(float2*)&Ps[(r0q + 8) * PS_PAD + nb * 8 + 2 * tg] = hi;
            }
            rs0 += __shfl_xor_sync(0xffffffffu, rs0, 1);
            rs0 += __shfl_xor_sync(0xffffffffu, rs0, 2);
            rs1 += __shfl_xor_sync(0xffffffffu, rs1, 1);
            rs1 += __shfl_xor_sync(0xffffffffu, rs1, 2);
            lrow0 = lrow0 * corr0 + rs0;
            lrow1 = lrow1 * corr1 + rs1;
            mrow0 = mn0; mrow1 = mn1;
            #pragma unroll
            for (int nb = 0; nb < 16; nb++) {
                of[nb][0] *= corr0; of[nb][1] *= corr0;
                of[nb][2] *= corr1; of[nb][3] *= corr1;
            }
            __syncwarp();  // Ps rows are warp-local

            // O += P . V  (16x128 per warp)
            #pragma unroll
            for (int ks = 0; ks < 8; ks++) {
                const int k = ks * 8;
                uint32_t pa[4];
                pa[0] = __float_as_uint(Ps[(r0q    ) * PS_PAD + k + tg    ]);
                pa[1] = __float_as_uint(Ps[(r0q + 8) * PS_PAD + k + tg    ]);
                pa[2] = __float_as_uint(Ps[(r0q    ) * PS_PAD + k + tg + 4]);
                pa[3] = __float_as_uint(Ps[(r0q + 8) * PS_PAD + k + tg + 4]);
                #pragma unroll
                for (int nb = 0; nb < 16; nb++) {
                    uint32_t b0 = __float_as_uint(Vc[(k + tg    ) * VS_PAD + nb * 8 + g]);
                    uint32_t b1 = __float_as_uint(Vc[(k + tg + 4) * VS_PAD + nb * 8 + g]);
                    mma_tf32(of[nb], pa, b0, b1);
                }
            }
        }

        // Normalize + store.
        float inv0 = 1.f / lrow0, inv1 = 1.f / lrow1;
        int r0 = m0 + r0q;
        #pragma unroll
        for (int nb = 0; nb < 16; nb++) {
            float2 lo = {of[nb][0] * inv0, of[nb][1] * inv0};
            float2 hi = {of[nb][2] * inv1, of[nb][3] * inv1};
            *(float2*)(out + ((size_t)b * Tdim + r0    ) * Hdim + nb * 8 + 2 * tg) = lo;
            *(float2*)(out + ((size_t)b * Tdim + r0 + 8) * Hdim + nb * 8 + 2 * tg) = hi;
        }
    }
    (void)srow; (void)sc4g;
}

// ---------------------------------------------------------------------------
extern "C" void kernel_launch(void* const* d_in, const int* in_sizes, int n_in,
                              void* d_out, int out_size)
{
    const float* x  = (const float*)d_in[0];
    const float* Wq = (const float*)d_in[1];
    const float* Wk = (const float*)d_in[2];
    const float* Wv = (const float*)d_in[3];
    float* out = (float*)d_out;

    const int qkv_smem = (2 * 128 * AS_PAD + 2 * 32 * BS_PAD) * (int)sizeof(float);
    cudaFuncSetAttribute(qkv_kernel,
                         cudaFuncAttributeMaxDynamicSharedMemorySize, qkv_smem);
    dim3 g1(BT / 128, 3);
    qkv_kernel<<<g1, 128, qkv_smem>>>(x, Wq, Wk, Wv);

    const int attn_smem = (64*QS_PAD + 2*64*KS_PAD + 2*64*VS_PAD + 64*PS_PAD)
                          * (int)sizeof(float);
    cudaFuncSetAttribute(attn_kernel,
                         cudaFuncAttributeMaxDynamicSharedMemorySize, attn_smem);
    dim3 g2(16, Bdim);
    attn_kernel<<<g2, 128, attn_smem>>>(out);
}